// round 8
// baseline (speedup 1.0000x reference)
#include <cuda_runtime.h>
#include <cuda_fp16.h>
#include <math.h>
#include <stdint.h>

#define NTOK 4096
#define DMODEL 1024
#define NEXP 8
#define TOPK 2
#define FDIM 4096

// ---------------- scratch (static device allocations; no cudaMalloc) ----------------
__device__ __half g_hh[NTOK * DMODEL];            // layernormed activations (fp16)
__device__ __half g_h1h[NTOK * TOPK * FDIM];      // GEMM1 output (gelu, fp16), grouped rows
__device__ float  g_y[NTOK * TOPK * DMODEL];      // GEMM2 split-0 partial (incl bias), *gate
__device__ float  g_y2[NTOK * TOPK * DMODEL];     // GEMM2 split-1 partial, *gate
__device__ __half g_W1h[NEXP * DMODEL * FDIM];    // W1 fp16, native layout [e][d][f]  ([k][n])
__device__ __half g_W2h[NEXP * FDIM * DMODEL];    // W2 fp16, native layout [e][f][d]  ([k][n])
__device__ int    g_cnt[NEXP];
__device__ int    g_cnt2[NEXP];
__device__ int    g_off[NEXP + 1];
__device__ int    g_rows[NTOK * TOPK];            // grouped row -> token
__device__ float  g_rowgate[NTOK * TOPK];         // grouped row -> gate
__device__ int    g_tok2row[NTOK * TOPK];         // (token, k) -> grouped row
__device__ int    g_tok_e[NTOK * TOPK];
__device__ float  g_tok_g[NTOK * TOPK];

// ---------------- helpers ----------------
__device__ __forceinline__ void mma_f16(float c[4], const unsigned a[4], const unsigned b[2]) {
    asm volatile(
        "mma.sync.aligned.m16n8k16.row.col.f32.f16.f16.f32 "
        "{%0,%1,%2,%3}, {%4,%5,%6,%7}, {%8,%9}, {%0,%1,%2,%3};\n"
        : "+f"(c[0]), "+f"(c[1]), "+f"(c[2]), "+f"(c[3])
        : "r"(a[0]), "r"(a[1]), "r"(a[2]), "r"(a[3]), "r"(b[0]), "r"(b[1]));
}

__device__ __forceinline__ void ldsm_x4(unsigned r[4], unsigned saddr) {
    asm volatile("ldmatrix.sync.aligned.m8n8.x4.shared.b16 {%0,%1,%2,%3}, [%4];"
                 : "=r"(r[0]), "=r"(r[1]), "=r"(r[2]), "=r"(r[3]) : "r"(saddr));
}
__device__ __forceinline__ void ldsm_x4_trans(unsigned r[4], unsigned saddr) {
    asm volatile("ldmatrix.sync.aligned.m8n8.x4.trans.shared.b16 {%0,%1,%2,%3}, [%4];"
                 : "=r"(r[0]), "=r"(r[1]), "=r"(r[2]), "=r"(r[3]) : "r"(saddr));
}

__device__ __forceinline__ float gelu_exact(float v) {
    return 0.5f * v * (1.0f + erff(v * 0.7071067811865475f));
}

__device__ __forceinline__ void cp_async16(unsigned smem_dst, const void* gmem_src, bool pred) {
    int sz = pred ? 16 : 0;
    asm volatile("cp.async.cg.shared.global [%0], [%1], 16, %2;\n"
                 :: "r"(smem_dst), "l"(gmem_src), "r"(sz));
}
__device__ __forceinline__ void cp_commit() {
    asm volatile("cp.async.commit_group;\n");
}
template <int N>
__device__ __forceinline__ void cp_wait() {
    asm volatile("cp.async.wait_group %0;\n" :: "n"(N));
}

// ---------------- kernel 0: zero counters ----------------
__global__ void zero_counts_kernel() {
    int t = threadIdx.x;
    if (t < NEXP) { g_cnt[t] = 0; g_cnt2[t] = 0; }
}

// ---------------- weight convert: fp32 -> fp16, same layout (streaming) ----------------
__global__ __launch_bounds__(256) void convert_fp16_kernel(
    const float* __restrict__ src, __half* __restrict__ dst)
{
    size_t i = ((size_t)blockIdx.x * blockDim.x + threadIdx.x) * 4;
    float4 v = *reinterpret_cast<const float4*>(src + i);
    __half2 h0 = __floats2half2_rn(v.x, v.y);
    __half2 h1 = __floats2half2_rn(v.z, v.w);
    *reinterpret_cast<__half2*>(dst + i)     = h0;
    *reinterpret_cast<__half2*>(dst + i + 2) = h1;
}

// ---------------- kernel 1: LayerNorm + router, register-resident ----------------
__global__ __launch_bounds__(256) void ln_router_kernel(
    const float* __restrict__ x, const float* __restrict__ ln_g,
    const float* __restrict__ ln_b, const float* __restrict__ Wr,
    const float* __restrict__ br)
{
    int n = blockIdx.x;
    const float* xr = x + (size_t)n * DMODEL;
    __shared__ float rs[8], rs2[8];
    __shared__ float rpart[8][8];     // [warp][expert]
    __shared__ float logit[NEXP];

    int tid = threadIdx.x;
    int w = tid >> 5, l = tid & 31;

    float v[4];
    float s = 0.f, s2 = 0.f;
#pragma unroll
    for (int i = 0; i < 4; i++) {
        v[i] = xr[tid + i * 256];
        s += v[i]; s2 += v[i] * v[i];
    }
#pragma unroll
    for (int o = 16; o; o >>= 1) {
        s  += __shfl_xor_sync(0xffffffffu, s, o);
        s2 += __shfl_xor_sync(0xffffffffu, s2, o);
    }
    if (l == 0) { rs[w] = s; rs2[w] = s2; }
    __syncthreads();
    if (tid == 0) {
        float a = 0.f, b = 0.f;
        for (int i = 0; i < 8; i++) { a += rs[i]; b += rs2[i]; }
        float mu = a / DMODEL;
        float var = b / DMODEL - mu * mu;
        rs[0] = mu;
        rs2[0] = rsqrtf(var + 1e-5f);
    }
    __syncthreads();
    float mu = rs[0], inv = rs2[0];

    float part[8];
#pragma unroll
    for (int e = 0; e < 8; e++) part[e] = 0.f;

#pragma unroll
    for (int i = 0; i < 4; i++) {
        int d = tid + i * 256;
        float h = (v[i] - mu) * inv * ln_g[d] + ln_b[d];
        g_hh[(size_t)n * DMODEL + d] = __float2half(h);
        float4 w0 = *reinterpret_cast<const float4*>(Wr + d * NEXP);
        float4 w1 = *reinterpret_cast<const float4*>(Wr + d * NEXP + 4);
        part[0] += h * w0.x; part[1] += h * w0.y; part[2] += h * w0.z; part[3] += h * w0.w;
        part[4] += h * w1.x; part[5] += h * w1.y; part[6] += h * w1.z; part[7] += h * w1.w;
    }
#pragma unroll
    for (int e = 0; e < 8; e++) {
#pragma unroll
        for (int o = 16; o; o >>= 1)
            part[e] += __shfl_xor_sync(0xffffffffu, part[e], o);
    }
    if (l == 0) {
#pragma unroll
        for (int e = 0; e < 8; e++) rpart[w][e] = part[e];
    }
    __syncthreads();
    if (tid < 8) {
        float a = 0.f;
#pragma unroll
        for (int i = 0; i < 8; i++) a += rpart[i][tid];
        logit[tid] = a + br[tid];
    }
    __syncthreads();

    if (tid == 0) {
        int i0 = 0;
        for (int e = 1; e < NEXP; e++) if (logit[e] > logit[i0]) i0 = e;
        int i1 = -1;
        for (int e = 0; e < NEXP; e++) {
            if (e == i0) continue;
            if (i1 < 0 || logit[e] > logit[i1]) i1 = e;
        }
        float v0 = logit[i0], v1 = logit[i1];
        float e1 = expf(v1 - v0);
        float denom = 1.0f + e1;
        float g0 = 1.0f / denom, g1 = e1 / denom;
        g_tok_e[n * 2 + 0] = i0;  g_tok_e[n * 2 + 1] = i1;
        g_tok_g[n * 2 + 0] = g0;  g_tok_g[n * 2 + 1] = g1;
        atomicAdd(&g_cnt[i0], 1);
        atomicAdd(&g_cnt[i1], 1);
    }
}

// ---------------- kernel 2: offsets ----------------
__global__ void calc_offsets_kernel() {
    if (threadIdx.x == 0) {
        int a = 0;
        for (int e = 0; e < NEXP; e++) { g_off[e] = a; a += g_cnt[e]; }
        g_off[NEXP] = a;
    }
}

// ---------------- kernel 3: assign grouped rows ----------------
__global__ void assign_rows_kernel() {
    int n = blockIdx.x * blockDim.x + threadIdx.x;
    if (n >= NTOK) return;
#pragma unroll
    for (int k = 0; k < TOPK; k++) {
        int e = g_tok_e[n * 2 + k];
        int pos = atomicAdd(&g_cnt2[e], 1);
        int row = g_off[e] + pos;
        g_rows[row] = n;
        g_rowgate[row] = g_tok_g[n * 2 + k];
        g_tok2row[n * 2 + k] = row;
    }
}

// ---------------- grouped GEMM: fp16 m16n8k16 + ldmatrix ----------------
// CTA tile 128x128xKC(=64), warp tile 64x32 (2m x 4n), 3-stage cp.async, 2 CTAs/SM.
// Single barrier per k-tile (top-of-loop barrier covers both hazards).
// PHASE 2 supports split-K via blockIdx.z = split*NEXP + e.
#define KC 64
#define APAD 72
#define BPAD 136
#define STAGE_HALVES (128 * APAD + KC * BPAD)
#define NSTAGES 3
#define GEMM_SMEM_BYTES (NSTAGES * STAGE_HALVES * 2)

template <int PHASE>
__global__ __launch_bounds__(256, 2) void moe_gemm_kernel(
    const __half* __restrict__ W, const float* __restrict__ bias)
{
    constexpr int KDIM = (PHASE == 1) ? DMODEL : FDIM;
    constexpr int NDIM = (PHASE == 1) ? FDIM : DMODEL;
    constexpr int KSEG = (PHASE == 1) ? KDIM : (KDIM / 2);   // split-K=2 for PHASE 2
    constexpr int KT = KSEG / KC;

    int e, split, kbase;
    if (PHASE == 2) {
        split = blockIdx.z >> 3;
        e = blockIdx.z & 7;
        kbase = split * KSEG;
    } else {
        split = 0; e = blockIdx.z; kbase = 0;
    }
    int off = g_off[e];
    int ne  = g_off[e + 1] - off;
    int m0  = blockIdx.y * 128;
    if (m0 >= ne) return;
    int n0  = blockIdx.x * 128;

    extern __shared__ __half smem[];
    unsigned sbase = (unsigned)__cvta_generic_to_shared(smem);

    int tid  = threadIdx.x;
    int warp = tid >> 5, lane = tid & 31;
    int wm = (warp >> 2) * 64;        // 2 warps in m
    int wn = (warp & 3) * 32;         // 4 warps in n
    int g8 = lane >> 2, tg = lane & 3;

    const __half* Wb = W + (size_t)e * (size_t)KDIM * NDIM;
    const __half* abase = (PHASE == 1) ? g_hh : g_h1h;

    // A row ids: 4 chunks per thread (128 rows x 8 chunks of 8 halves = 1024)
    int arow[4];
    bool apred[4];
#pragma unroll
    for (int i = 0; i < 4; i++) {
        int u = tid + i * 256;
        int r = u >> 3;
        apred[i] = (m0 + r) < ne;
        int gm = apred[i] ? (off + m0 + r) : off;
        arow[i] = (PHASE == 1) ? g_rows[gm] : gm;
    }

    // ldmatrix per-lane base offsets (bytes)
    unsigned a_off = ((wm + (lane & 15)) * APAD + ((lane >> 4) << 3)) * 2;
    unsigned b_off = (((lane & 15)) * BPAD + wn + ((lane >> 4) << 3)) * 2;

    float acc[4][4][4];
#pragma unroll
    for (int mi = 0; mi < 4; mi++)
#pragma unroll
        for (int ni = 0; ni < 4; ni++)
#pragma unroll
            for (int c = 0; c < 4; c++) acc[mi][ni][c] = 0.f;

    auto load_tile = [&](int stage, int kt) {
        unsigned sA = sbase + stage * STAGE_HALVES * 2;
        unsigned sB = sA + 128 * APAD * 2;
        int k0 = kbase + kt * KC;
        // A: 128 rows x 64 halves; 8 chunks/row; 1024 chunks; 4 per thread
#pragma unroll
        for (int i = 0; i < 4; i++) {
            int u = tid + i * 256;
            int r = u >> 3, c = u & 7;
            const __half* src = abase + (size_t)arow[i] * KDIM + k0 + c * 8;
            cp_async16(sA + (r * APAD + c * 8) * 2, src, apred[i]);
        }
        // B: 64 k-rows x 128 n halves (native [k][n]); 16 chunks/row; 1024 chunks; 4 per thread
#pragma unroll
        for (int i = 0; i < 4; i++) {
            int u = tid + i * 256;
            int kk = u >> 4, c = u & 15;
            const __half* src = Wb + (size_t)(k0 + kk) * NDIM + n0 + c * 8;
            cp_async16(sB + (kk * BPAD + c * 8) * 2, src, true);
        }
    };

    // prologue
#pragma unroll
    for (int s = 0; s < NSTAGES - 1; s++) {
        load_tile(s, s);
        cp_commit();
    }

    // mainloop — single barrier per iteration:
    //   BAR separates compute(kt-1) [reads stage (kt-1)%3] from load(kt) [writes (kt+2)%3 == (kt-1)%3]
    for (int kt = 0; kt < KT; kt++) {
        cp_wait<NSTAGES - 2>();
        __syncthreads();

        int nxt = kt + NSTAGES - 1;
        if (nxt < KT) load_tile(nxt % NSTAGES, nxt);
        cp_commit();

        unsigned sA = sbase + (kt % NSTAGES) * STAGE_HALVES * 2;
        unsigned sB = sA + 128 * APAD * 2;

#pragma unroll
        for (int ks = 0; ks < KC; ks += 16) {
            unsigned a[4][4];
#pragma unroll
            for (int mi = 0; mi < 4; mi++)
                ldsm_x4(a[mi], sA + a_off + (mi * 16 * APAD + ks) * 2);
            unsigned b[4][2];
#pragma unroll
            for (int nseg = 0; nseg < 2; nseg++) {
                unsigned r[4];
                ldsm_x4_trans(r, sB + b_off + (ks * BPAD + nseg * 16) * 2);
                b[nseg * 2 + 0][0] = r[0]; b[nseg * 2 + 0][1] = r[1];
                b[nseg * 2 + 1][0] = r[2]; b[nseg * 2 + 1][1] = r[3];
            }
#pragma unroll
            for (int mi = 0; mi < 4; mi++)
#pragma unroll
                for (int ni = 0; ni < 4; ni++)
                    mma_f16(acc[mi][ni], a[mi], b[ni]);
        }
    }

    // ---- epilogue ----
    float* yout = (PHASE == 2) ? (split ? g_y2 : g_y) : nullptr;
    bool addb = (PHASE == 1) || (split == 0);
#pragma unroll
    for (int mi = 0; mi < 4; mi++) {
#pragma unroll
        for (int half = 0; half < 2; half++) {
            int ml = wm + mi * 16 + g8 + half * 8;
            if (m0 + ml >= ne) continue;
            int gm = off + m0 + ml;
            float gate = (PHASE == 2) ? g_rowgate[gm] : 0.f;
#pragma unroll
            for (int ni = 0; ni < 4; ni++) {
                int nn = n0 + wn + ni * 8 + tg * 2;
                float v0 = acc[mi][ni][half * 2 + 0];
                float v1 = acc[mi][ni][half * 2 + 1];
                if (PHASE == 1) {
                    v0 = gelu_exact(v0 + bias[e * FDIM + nn]);
                    v1 = gelu_exact(v1 + bias[e * FDIM + nn + 1]);
                    *(__half2*)(g_h1h + (size_t)gm * FDIM + nn) = __floats2half2_rn(v0, v1);
                } else {
                    float b0 = addb ? bias[e * DMODEL + nn]     : 0.f;
                    float b1 = addb ? bias[e * DMODEL + nn + 1] : 0.f;
                    v0 = (v0 + b0) * gate;
                    v1 = (v1 + b1) * gate;
                    *(float2*)(yout + (size_t)gm * DMODEL + nn) = make_float2(v0, v1);
                }
            }
        }
    }
}

// ---------------- finalize: out = x + sum over slots and splits ----------------
__global__ void finalize_kernel(const float* __restrict__ x, float* __restrict__ out) {
    int i = blockIdx.x * blockDim.x + threadIdx.x;
    if (i >= NTOK * DMODEL / 4) return;
    int n = i / (DMODEL / 4), ds = i % (DMODEL / 4);
    int r0 = g_tok2row[2 * n], r1 = g_tok2row[2 * n + 1];
    float4 xv = reinterpret_cast<const float4*>(x)[i];
    float4 a  = reinterpret_cast<const float4*>(g_y )[(size_t)r0 * (DMODEL / 4) + ds];
    float4 a2 = reinterpret_cast<const float4*>(g_y2)[(size_t)r0 * (DMODEL / 4) + ds];
    float4 b  = reinterpret_cast<const float4*>(g_y )[(size_t)r1 * (DMODEL / 4) + ds];
    float4 b2 = reinterpret_cast<const float4*>(g_y2)[(size_t)r1 * (DMODEL / 4) + ds];
    float4 o;
    o.x = xv.x + (a.x + a2.x) + (b.x + b2.x);
    o.y = xv.y + (a.y + a2.y) + (b.y + b2.y);
    o.z = xv.z + (a.z + a2.z) + (b.z + b2.z);
    o.w = xv.w + (a.w + a2.w) + (b.w + b2.w);
    reinterpret_cast<float4*>(out)[i] = o;
}

// ---------------- launch ----------------
extern "C" void kernel_launch(void* const* d_in, const int* in_sizes, int n_in,
                              void* d_out, int out_size)
{
    const float* x    = (const float*)d_in[0];
    const float* ln_g = (const float*)d_in[1];
    const float* ln_b = (const float*)d_in[2];
    const float* Wr   = (const float*)d_in[3];
    const float* br   = (const float*)d_in[4];
    const float* W1   = (const float*)d_in[5];
    const float* b1   = (const float*)d_in[6];
    const float* W2   = (const float*)d_in[7];
    const float* b2   = (const float*)d_in[8];
    float* out = (float*)d_out;

    cudaFuncSetAttribute(moe_gemm_kernel<1>,
                         cudaFuncAttributeMaxDynamicSharedMemorySize, GEMM_SMEM_BYTES);
    cudaFuncSetAttribute(moe_gemm_kernel<2>,
                         cudaFuncAttributeMaxDynamicSharedMemorySize, GEMM_SMEM_BYTES);

    __half* W1h; cudaGetSymbolAddress((void**)&W1h, g_W1h);
    __half* W2h; cudaGetSymbolAddress((void**)&W2h, g_W2h);

    const size_t WELEMS = (size_t)NEXP * DMODEL * FDIM;

    zero_counts_kernel<<<1, 32>>>();
    convert_fp16_kernel<<<(unsigned)(WELEMS / 4 / 256), 256>>>(W1, W1h);
    convert_fp16_kernel<<<(unsigned)(WELEMS / 4 / 256), 256>>>(W2, W2h);
    ln_router_kernel<<<NTOK, 256>>>(x, ln_g, ln_b, Wr, br);
    calc_offsets_kernel<<<1, 32>>>();
    assign_rows_kernel<<<(NTOK + 255) / 256, 256>>>();
    moe_gemm_kernel<1><<<dim3(FDIM / 128, NTOK * TOPK / 128, NEXP), 256, GEMM_SMEM_BYTES>>>(W1h, b1);
    moe_gemm_kernel<2><<<dim3(DMODEL / 128, NTOK * TOPK / 128, NEXP * 2), 256, GEMM_SMEM_BYTES>>>(W2h, b2);
    finalize_kernel<<<(NTOK * DMODEL / 4 + 255) / 256, 256>>>(x, out);
}

// round 9
// speedup vs baseline: 1.0423x; 1.0423x over previous
#include <cuda_runtime.h>
#include <cuda_fp16.h>
#include <math.h>
#include <stdint.h>

#define NTOK 4096
#define DMODEL 1024
#define NEXP 8
#define TOPK 2
#define FDIM 4096

// ---------------- scratch (static device allocations; no cudaMalloc) ----------------
__device__ __half g_hh[NTOK * DMODEL];            // layernormed activations (fp16)
__device__ __half g_h1h[NTOK * TOPK * FDIM];      // GEMM1 output (gelu, fp16), grouped rows
__device__ float  g_y[NTOK * TOPK * DMODEL];      // GEMM2 output * gate (fp32), grouped rows
__device__ __half g_W1h[NEXP * DMODEL * FDIM];    // W1 fp16, native layout [e][d][f]  ([k][n])
__device__ __half g_W2h[NEXP * FDIM * DMODEL];    // W2 fp16, native layout [e][f][d]  ([k][n])
__device__ int    g_cnt[NEXP];
__device__ int    g_cnt2[NEXP];
__device__ int    g_off[NEXP + 1];
__device__ int    g_rows[NTOK * TOPK];            // grouped row -> token
__device__ float  g_rowgate[NTOK * TOPK];         // grouped row -> gate
__device__ int    g_tok2row[NTOK * TOPK];         // (token, k) -> grouped row
__device__ int    g_tok_e[NTOK * TOPK];
__device__ float  g_tok_g[NTOK * TOPK];

// ---------------- helpers ----------------
__device__ __forceinline__ void mma_f16(float c[4], const unsigned a[4], const unsigned b[2]) {
    asm volatile(
        "mma.sync.aligned.m16n8k16.row.col.f32.f16.f16.f32 "
        "{%0,%1,%2,%3}, {%4,%5,%6,%7}, {%8,%9}, {%0,%1,%2,%3};\n"
        : "+f"(c[0]), "+f"(c[1]), "+f"(c[2]), "+f"(c[3])
        : "r"(a[0]), "r"(a[1]), "r"(a[2]), "r"(a[3]), "r"(b[0]), "r"(b[1]));
}

__device__ __forceinline__ void ldsm_x4(unsigned r[4], unsigned saddr) {
    asm volatile("ldmatrix.sync.aligned.m8n8.x4.shared.b16 {%0,%1,%2,%3}, [%4];"
                 : "=r"(r[0]), "=r"(r[1]), "=r"(r[2]), "=r"(r[3]) : "r"(saddr));
}
__device__ __forceinline__ void ldsm_x4_trans(unsigned r[4], unsigned saddr) {
    asm volatile("ldmatrix.sync.aligned.m8n8.x4.trans.shared.b16 {%0,%1,%2,%3}, [%4];"
                 : "=r"(r[0]), "=r"(r[1]), "=r"(r[2]), "=r"(r[3]) : "r"(saddr));
}

__device__ __forceinline__ float gelu_exact(float v) {
    return 0.5f * v * (1.0f + erff(v * 0.7071067811865475f));
}

__device__ __forceinline__ void cp_async16(unsigned smem_dst, const void* gmem_src, bool pred) {
    int sz = pred ? 16 : 0;
    asm volatile("cp.async.cg.shared.global [%0], [%1], 16, %2;\n"
                 :: "r"(smem_dst), "l"(gmem_src), "r"(sz));
}
__device__ __forceinline__ void cp_commit() {
    asm volatile("cp.async.commit_group;\n");
}
template <int N>
__device__ __forceinline__ void cp_wait() {
    asm volatile("cp.async.wait_group %0;\n" :: "n"(N));
}

__device__ __forceinline__ void cvt4(const float* __restrict__ src, __half* __restrict__ dst,
                                     size_t idx4) {
    float4 v = reinterpret_cast<const float4*>(src)[idx4];
    __half2 h0 = __floats2half2_rn(v.x, v.y);
    __half2 h1 = __floats2half2_rn(v.z, v.w);
    reinterpret_cast<__half2*>(dst)[idx4 * 2]     = h0;
    reinterpret_cast<__half2*>(dst)[idx4 * 2 + 1] = h1;
}

// ---------------- kernel 0: zero counters ----------------
__global__ void zero_counts_kernel() {
    int t = threadIdx.x;
    if (t < NEXP) { g_cnt[t] = 0; g_cnt2[t] = 0; }
}

// ---------------- kernel 1: LayerNorm + router + W1 convert (fused) ----------------
__global__ __launch_bounds__(256) void ln_router_kernel(
    const float* __restrict__ x, const float* __restrict__ ln_g,
    const float* __restrict__ ln_b, const float* __restrict__ Wr,
    const float* __restrict__ br, const float* __restrict__ W1_f32)
{
    int n = blockIdx.x;
    const float* xr = x + (size_t)n * DMODEL;
    __shared__ float rs[8], rs2[8];
    __shared__ float rpart[8][8];     // [warp][expert]
    __shared__ float logit[NEXP];

    int tid = threadIdx.x;
    int w = tid >> 5, l = tid & 31;

    float v[4];
    float s = 0.f, s2 = 0.f;
#pragma unroll
    for (int i = 0; i < 4; i++) {
        v[i] = xr[tid + i * 256];
        s += v[i]; s2 += v[i] * v[i];
    }
#pragma unroll
    for (int o = 16; o; o >>= 1) {
        s  += __shfl_xor_sync(0xffffffffu, s, o);
        s2 += __shfl_xor_sync(0xffffffffu, s2, o);
    }
    if (l == 0) { rs[w] = s; rs2[w] = s2; }
    __syncthreads();
    if (tid == 0) {
        float a = 0.f, b = 0.f;
        for (int i = 0; i < 8; i++) { a += rs[i]; b += rs2[i]; }
        float mu = a / DMODEL;
        float var = b / DMODEL - mu * mu;
        rs[0] = mu;
        rs2[0] = rsqrtf(var + 1e-5f);
    }
    __syncthreads();
    float mu = rs[0], inv = rs2[0];

    float part[8];
#pragma unroll
    for (int e = 0; e < 8; e++) part[e] = 0.f;

#pragma unroll
    for (int i = 0; i < 4; i++) {
        int d = tid + i * 256;
        float h = (v[i] - mu) * inv * ln_g[d] + ln_b[d];
        g_hh[(size_t)n * DMODEL + d] = __float2half(h);
        float4 w0 = *reinterpret_cast<const float4*>(Wr + d * NEXP);
        float4 w1 = *reinterpret_cast<const float4*>(Wr + d * NEXP + 4);
        part[0] += h * w0.x; part[1] += h * w0.y; part[2] += h * w0.z; part[3] += h * w0.w;
        part[4] += h * w1.x; part[5] += h * w1.y; part[6] += h * w1.z; part[7] += h * w1.w;
    }
#pragma unroll
    for (int e = 0; e < 8; e++) {
#pragma unroll
        for (int o = 16; o; o >>= 1)
            part[e] += __shfl_xor_sync(0xffffffffu, part[e], o);
    }
    if (l == 0) {
#pragma unroll
        for (int e = 0; e < 8; e++) rpart[w][e] = part[e];
    }
    __syncthreads();
    if (tid < 8) {
        float a = 0.f;
#pragma unroll
        for (int i = 0; i < 8; i++) a += rpart[i][tid];
        logit[tid] = a + br[tid];
    }
    __syncthreads();

    if (tid == 0) {
        int i0 = 0;
        for (int e = 1; e < NEXP; e++) if (logit[e] > logit[i0]) i0 = e;
        int i1 = -1;
        for (int e = 0; e < NEXP; e++) {
            if (e == i0) continue;
            if (i1 < 0 || logit[e] > logit[i1]) i1 = e;
        }
        float v0 = logit[i0], v1 = logit[i1];
        float e1 = expf(v1 - v0);
        float denom = 1.0f + e1;
        float g0 = 1.0f / denom, g1 = e1 / denom;
        g_tok_e[n * 2 + 0] = i0;  g_tok_e[n * 2 + 1] = i1;
        g_tok_g[n * 2 + 0] = g0;  g_tok_g[n * 2 + 1] = g1;
        atomicAdd(&g_cnt[i0], 1);
        atomicAdd(&g_cnt[i1], 1);
    }

    // ---- fused W1 fp32->fp16 convert: block n handles float4s [n*2048, (n+1)*2048) ----
    {
        size_t base = (size_t)n * 2048 + tid;
#pragma unroll
        for (int i = 0; i < 8; i++)
            cvt4(W1_f32, g_W1h, base + i * 256);
    }
}

// ---------------- kernel 2: offsets ----------------
__global__ void calc_offsets_kernel() {
    if (threadIdx.x == 0) {
        int a = 0;
        for (int e = 0; e < NEXP; e++) { g_off[e] = a; a += g_cnt[e]; }
        g_off[NEXP] = a;
    }
}

// ---------------- kernel 3: assign grouped rows ----------------
__global__ void assign_rows_kernel() {
    int n = blockIdx.x * blockDim.x + threadIdx.x;
    if (n >= NTOK) return;
#pragma unroll
    for (int k = 0; k < TOPK; k++) {
        int e = g_tok_e[n * 2 + k];
        int pos = atomicAdd(&g_cnt2[e], 1);
        int row = g_off[e] + pos;
        g_rows[row] = n;
        g_rowgate[row] = g_tok_g[n * 2 + k];
        g_tok2row[n * 2 + k] = row;
    }
}

// ---------------- grouped GEMM: fp16 m16n8k16 + ldmatrix ----------------
// CTA tile 128x128xKC(=64), warp tile 64x32 (2m x 4n), 3-stage cp.async, 2 CTAs/SM.
// Single barrier per k-tile. PHASE 1 additionally converts a W2 chunk per CTA
// (16384 CTAs x 2048 elems = full W2), overlapped with GEMM compute.
#define KC 64
#define APAD 72
#define BPAD 136
#define STAGE_HALVES (128 * APAD + KC * BPAD)
#define NSTAGES 3
#define GEMM_SMEM_BYTES (NSTAGES * STAGE_HALVES * 2)

template <int PHASE>
__global__ __launch_bounds__(256, 2) void moe_gemm_kernel(
    const __half* __restrict__ W, const float* __restrict__ bias,
    const float* __restrict__ cvt_src, __half* __restrict__ cvt_dst)
{
    constexpr int KDIM = (PHASE == 1) ? DMODEL : FDIM;
    constexpr int NDIM = (PHASE == 1) ? FDIM : DMODEL;
    constexpr int KT = KDIM / KC;

    int tid  = threadIdx.x;

    // ---- PHASE 1: convert this CTA's W2 chunk (runs for ALL CTAs, incl. early-exit) ----
    if (PHASE == 1) {
        size_t bid = blockIdx.x + (size_t)gridDim.x * (blockIdx.y + (size_t)gridDim.y * blockIdx.z);
        size_t base = bid * 512 + tid;     // 512 float4 per CTA (2048 elems)
        cvt4(cvt_src, cvt_dst, base);
        cvt4(cvt_src, cvt_dst, base + 256);
    }

    int e = blockIdx.z;
    int off = g_off[e];
    int ne  = g_off[e + 1] - off;
    int m0  = blockIdx.y * 128;
    if (m0 >= ne) return;
    int n0  = blockIdx.x * 128;

    extern __shared__ __half smem[];
    unsigned sbase = (unsigned)__cvta_generic_to_shared(smem);

    int warp = tid >> 5, lane = tid & 31;
    int wm = (warp >> 2) * 64;        // 2 warps in m
    int wn = (warp & 3) * 32;         // 4 warps in n
    int g8 = lane >> 2, tg = lane & 3;

    const __half* Wb = W + (size_t)e * (size_t)KDIM * NDIM;
    const __half* abase = (PHASE == 1) ? g_hh : g_h1h;

    // A row ids: 4 chunks per thread (128 rows x 8 chunks of 8 halves = 1024)
    int arow[4];
    bool apred[4];
#pragma unroll
    for (int i = 0; i < 4; i++) {
        int u = tid + i * 256;
        int r = u >> 3;
        apred[i] = (m0 + r) < ne;
        int gm = apred[i] ? (off + m0 + r) : off;
        arow[i] = (PHASE == 1) ? g_rows[gm] : gm;
    }

    // ldmatrix per-lane base offsets (bytes)
    unsigned a_off = ((wm + (lane & 15)) * APAD + ((lane >> 4) << 3)) * 2;
    unsigned b_off = (((lane & 15)) * BPAD + wn + ((lane >> 4) << 3)) * 2;

    float acc[4][4][4];
#pragma unroll
    for (int mi = 0; mi < 4; mi++)
#pragma unroll
        for (int ni = 0; ni < 4; ni++)
#pragma unroll
            for (int c = 0; c < 4; c++) acc[mi][ni][c] = 0.f;

    auto load_tile = [&](int stage, int kt) {
        unsigned sA = sbase + stage * STAGE_HALVES * 2;
        unsigned sB = sA + 128 * APAD * 2;
        int k0 = kt * KC;
        // A: 128 rows x 64 halves; 8 chunks/row; 1024 chunks; 4 per thread
#pragma unroll
        for (int i = 0; i < 4; i++) {
            int u = tid + i * 256;
            int r = u >> 3, c = u & 7;
            const __half* src = abase + (size_t)arow[i] * KDIM + k0 + c * 8;
            cp_async16(sA + (r * APAD + c * 8) * 2, src, apred[i]);
        }
        // B: 64 k-rows x 128 n halves (native [k][n]); 16 chunks/row; 1024 chunks; 4 per thread
#pragma unroll
        for (int i = 0; i < 4; i++) {
            int u = tid + i * 256;
            int kk = u >> 4, c = u & 15;
            const __half* src = Wb + (size_t)(k0 + kk) * NDIM + n0 + c * 8;
            cp_async16(sB + (kk * BPAD + c * 8) * 2, src, true);
        }
    };

    // prologue
#pragma unroll
    for (int s = 0; s < NSTAGES - 1; s++) {
        load_tile(s, s);
        cp_commit();
    }

    // mainloop — single barrier per iteration (top barrier covers both smem hazards)
    for (int kt = 0; kt < KT; kt++) {
        cp_wait<NSTAGES - 2>();
        __syncthreads();

        int nxt = kt + NSTAGES - 1;
        if (nxt < KT) load_tile(nxt % NSTAGES, nxt);
        cp_commit();

        unsigned sA = sbase + (kt % NSTAGES) * STAGE_HALVES * 2;
        unsigned sB = sA + 128 * APAD * 2;

#pragma unroll
        for (int ks = 0; ks < KC; ks += 16) {
            unsigned a[4][4];
#pragma unroll
            for (int mi = 0; mi < 4; mi++)
                ldsm_x4(a[mi], sA + a_off + (mi * 16 * APAD + ks) * 2);
            unsigned b[4][2];
#pragma unroll
            for (int nseg = 0; nseg < 2; nseg++) {
                unsigned r[4];
                ldsm_x4_trans(r, sB + b_off + (ks * BPAD + nseg * 16) * 2);
                b[nseg * 2 + 0][0] = r[0]; b[nseg * 2 + 0][1] = r[1];
                b[nseg * 2 + 1][0] = r[2]; b[nseg * 2 + 1][1] = r[3];
            }
#pragma unroll
            for (int mi = 0; mi < 4; mi++)
#pragma unroll
                for (int ni = 0; ni < 4; ni++)
                    mma_f16(acc[mi][ni], a[mi], b[ni]);
        }
    }

    // ---- epilogue ----
#pragma unroll
    for (int mi = 0; mi < 4; mi++) {
#pragma unroll
        for (int half = 0; half < 2; half++) {
            int ml = wm + mi * 16 + g8 + half * 8;
            if (m0 + ml >= ne) continue;
            int gm = off + m0 + ml;
            float gate = (PHASE == 2) ? g_rowgate[gm] : 0.f;
#pragma unroll
            for (int ni = 0; ni < 4; ni++) {
                int nn = n0 + wn + ni * 8 + tg * 2;
                float v0 = acc[mi][ni][half * 2 + 0];
                float v1 = acc[mi][ni][half * 2 + 1];
                if (PHASE == 1) {
                    v0 = gelu_exact(v0 + bias[e * FDIM + nn]);
                    v1 = gelu_exact(v1 + bias[e * FDIM + nn + 1]);
                    *(__half2*)(g_h1h + (size_t)gm * FDIM + nn) = __floats2half2_rn(v0, v1);
                } else {
                    v0 = (v0 + bias[e * DMODEL + nn]) * gate;
                    v1 = (v1 + bias[e * DMODEL + nn + 1]) * gate;
                    *(float2*)(g_y + (size_t)gm * DMODEL + nn) = make_float2(v0, v1);
                }
            }
        }
    }
}

// ---------------- finalize: out = x + y[slot0] + y[slot1] ----------------
__global__ void finalize_kernel(const float* __restrict__ x, float* __restrict__ out) {
    int i = blockIdx.x * blockDim.x + threadIdx.x;
    if (i >= NTOK * DMODEL / 4) return;
    int n = i / (DMODEL / 4), ds = i % (DMODEL / 4);
    int r0 = g_tok2row[2 * n], r1 = g_tok2row[2 * n + 1];
    float4 xv = reinterpret_cast<const float4*>(x)[i];
    float4 a = reinterpret_cast<const float4*>(g_y)[(size_t)r0 * (DMODEL / 4) + ds];
    float4 b = reinterpret_cast<const float4*>(g_y)[(size_t)r1 * (DMODEL / 4) + ds];
    float4 o;
    o.x = xv.x + a.x + b.x;
    o.y = xv.y + a.y + b.y;
    o.z = xv.z + a.z + b.z;
    o.w = xv.w + a.w + b.w;
    reinterpret_cast<float4*>(out)[i] = o;
}

// ---------------- launch ----------------
extern "C" void kernel_launch(void* const* d_in, const int* in_sizes, int n_in,
                              void* d_out, int out_size)
{
    const float* x    = (const float*)d_in[0];
    const float* ln_g = (const float*)d_in[1];
    const float* ln_b = (const float*)d_in[2];
    const float* Wr   = (const float*)d_in[3];
    const float* br   = (const float*)d_in[4];
    const float* W1   = (const float*)d_in[5];
    const float* b1   = (const float*)d_in[6];
    const float* W2   = (const float*)d_in[7];
    const float* b2   = (const float*)d_in[8];
    float* out = (float*)d_out;

    cudaFuncSetAttribute(moe_gemm_kernel<1>,
                         cudaFuncAttributeMaxDynamicSharedMemorySize, GEMM_SMEM_BYTES);
    cudaFuncSetAttribute(moe_gemm_kernel<2>,
                         cudaFuncAttributeMaxDynamicSharedMemorySize, GEMM_SMEM_BYTES);

    __half* W1h; cudaGetSymbolAddress((void**)&W1h, g_W1h);
    __half* W2h; cudaGetSymbolAddress((void**)&W2h, g_W2h);

    zero_counts_kernel<<<1, 32>>>();
    ln_router_kernel<<<NTOK, 256>>>(x, ln_g, ln_b, Wr, br, W1);
    calc_offsets_kernel<<<1, 32>>>();
    assign_rows_kernel<<<(NTOK + 255) / 256, 256>>>();
    moe_gemm_kernel<1><<<dim3(FDIM / 128, NTOK * TOPK / 128, NEXP), 256, GEMM_SMEM_BYTES>>>(
        W1h, b1, W2, W2h);
    moe_gemm_kernel<2><<<dim3(DMODEL / 128, NTOK * TOPK / 128, NEXP), 256, GEMM_SMEM_BYTES>>>(
        W2h, b2, nullptr, nullptr);
    finalize_kernel<<<(NTOK * DMODEL / 4 + 255) / 256, 256>>>(x, out);
}